// round 13
// baseline (speedup 1.0000x reference)
#include <cuda_runtime.h>
#include <cuda_fp16.h>
#include <cstdint>
#include <cstddef>

#define D1 64
#define D2 64
#define BB 32
#define II 64
#define OO 128
#define M_TOT (D1 * D2 * BB)   // 131072

// Packed pre-activations (R7 layout): [cell m][word p=0..2][o=0..127] uint32.
// word0 = (f0,f1), word1 = (i,o), word2 = (c,pad). Bias folded in.
#define NPW 384
#define WSTRIDE (32 * NPW)     // advance one grid position (fixed b) = 12288
__device__ uint32_t g_pk[(size_t)M_TOT * NPW];
__device__ int g_flags[64];    // per-d1 completed GEMM tile count (target 32)

// ========================= helpers =========================
__device__ __forceinline__ uint32_t smem_u32(const void* p) {
    uint32_t a;
    asm("{ .reg .u64 t; cvta.to.shared.u64 t, %1; cvt.u32.u64 %0, t; }"
        : "=r"(a) : "l"(p));
    return a;
}
__device__ __forceinline__ void ldsm_x4(uint32_t& r0, uint32_t& r1,
                                        uint32_t& r2, uint32_t& r3,
                                        uint32_t addr) {
    asm volatile("ldmatrix.sync.aligned.m8n8.x4.shared.b16 {%0,%1,%2,%3}, [%4];"
                 : "=r"(r0), "=r"(r1), "=r"(r2), "=r"(r3) : "r"(addr));
}
__device__ __forceinline__ void mma_f16(float* d, const uint32_t* a,
                                        uint32_t b0, uint32_t b1) {
    asm volatile(
        "mma.sync.aligned.m16n8k16.row.col.f32.f16.f16.f32 "
        "{%0,%1,%2,%3}, {%4,%5,%6,%7}, {%8,%9}, {%0,%1,%2,%3};"
        : "+f"(d[0]), "+f"(d[1]), "+f"(d[2]), "+f"(d[3])
        : "r"(a[0]), "r"(a[1]), "r"(a[2]), "r"(a[3]), "r"(b0), "r"(b1));
}
__device__ __forceinline__ uint32_t h1(float v) {
    __half h = __float2half_rn(v);
    return (uint32_t)(*reinterpret_cast<unsigned short*>(&h));
}
__device__ __forceinline__ uint32_t packh2(float a, float b) {
    __half2 h = __floats2half2_rn(a, b);
    return *reinterpret_cast<uint32_t*>(&h);
}
__device__ __forceinline__ float2 up2(uint32_t w) {
    __half2 h = *reinterpret_cast<__half2*>(&w);
    return __half22float2(h);
}
__device__ __forceinline__ float tanhapx(float x) {
    float y;
    asm("tanh.approx.f32 %0, %1;" : "=f"(y) : "f"(x));
    return y;
}
__device__ __forceinline__ float sigf(float x) {   // R7 exact
    float t;
    asm("tanh.approx.f32 %0, %1;" : "=f"(t) : "f"(0.5f * x));
    return fmaf(0.5f, t, 0.5f);
}
// plain (coherent-path) global load; ordered after acquire loads
__device__ __forceinline__ uint32_t ldg_plain(const uint32_t* p) {
    uint32_t v;
    asm volatile("ld.global.b32 %0, [%1];" : "=r"(v) : "l"(p));
    return v;
}
__device__ __forceinline__ int ld_acq_gpu(const int* p) {
    int v;
    asm volatile("ld.acquire.gpu.s32 %0, [%1];" : "=r"(v) : "l"(p) : "memory");
    return v;
}
#define SPIN_GE(addr, target) do {                                          \
    int _v;                                                                 \
    asm volatile("ld.acquire.cta.shared.b32 %0, [%1];"                      \
                 : "=r"(_v) : "r"(addr) : "memory");                        \
    while (_v < (target)) {                                                 \
        asm volatile("nanosleep.u32 32;");                                  \
        asm volatile("ld.acquire.cta.shared.b32 %0, [%1];"                  \
                     : "=r"(_v) : "r"(addr) : "memory");                    \
    }                                                                       \
} while (0)
#define ST_REL(addr, val)                                                   \
    asm volatile("st.release.cta.shared.b32 [%0], %1;"                      \
                 :: "r"(addr), "r"(val) : "memory")

__device__ __forceinline__ void waitflag(int row) {
    const int* fp = g_flags + row;
    while (ld_acq_gpu(fp) < 32) { asm volatile("nanosleep.u32 256;"); }
}

struct UC {
    float uf00, uf01, uf10, uf11;
    float ui0, ui1, uo0, uo1, uc0, uc1;
};

__device__ __forceinline__ void cell_w(const uint32_t qw[3], const UC& u,
                                       float hup, float hl,
                                       float sup, float sl,
                                       float& s, float& h)
{
    float2 qa = up2(qw[0]);   // (f0, f1)
    float2 qb = up2(qw[1]);   // (i, o)
    float2 qc = up2(qw[2]);   // (c, pad)
    float pf0 = fmaf(u.uf01, hl, fmaf(u.uf00, hup, qa.x));
    float pf1 = fmaf(u.uf11, hl, fmaf(u.uf10, hup, qa.y));
    float pi  = fmaf(u.ui1,  hl, fmaf(u.ui0,  hup, qb.x));
    float po  = fmaf(u.uo1,  hl, fmaf(u.uo0,  hup, qb.y));
    float pc  = fmaf(u.uc1,  hl, fmaf(u.uc0,  hup, qc.x));
    float f0 = sigf(pf0);
    float f1 = sigf(pf1);
    float ig = sigf(pi);
    float og = sigf(po);
    float cg = sigf(pc);
    s = fmaf(f0, sup, fmaf(f1, sl, ig * cg));
    h = og * tanhapx(s);
}

// ================= init kernel: zero flags (fresh every replay) ============
__global__ void init_flags() { g_flags[threadIdx.x] = 0; }

// ================= combined kernel =================
// blocks 0..127: REC (b = bid>>2, og = bid&3); 8 warps x 8 rows.
// blocks 128..2175: GEMM tile of 64 m-rows; d1 = tile>>5 ascending.
#define A_STR 72
#define B_STR 72
#define SM_A 0
#define SM_B 9216                        // + g*18432
#define SM_TOTAL (9216 + 5 * 18432)      // 101376
// REC smem overlay (first 8.3 KB of the same dynamic array):
#define SHS_OFF 0u                       // [4][8][32] f32 = 4096
#define SHH_OFF 4096u
#define RDY_OFF 8192u                    // 8 ints

__global__ void __launch_bounds__(256, 2) mdlstm_combined(
    const float* __restrict__ X,
    const float* __restrict__ wf, const float* __restrict__ uf,
    const float* __restrict__ biasf,
    const float* __restrict__ wi, const float* __restrict__ ui,
    const float* __restrict__ biasi,
    const float* __restrict__ wo, const float* __restrict__ uo,
    const float* __restrict__ biaso,
    const float* __restrict__ wc, const float* __restrict__ uc,
    const float* __restrict__ biasc,
    float* __restrict__ out)
{
    extern __shared__ __align__(1024) char sm[];
    const uint32_t sbase = smem_u32(sm);
    const int tid  = threadIdx.x;
    const int lane = tid & 31;
    const int w    = tid >> 5;          // 0..7

    if (blockIdx.x < 128) {
        // ========================= REC =========================
        const int b  = blockIdx.x >> 2;
        const int og = blockIdx.x & 3;
        const int o  = og * 32 + lane;
        const int R8 = 8 * w;           // first row of this warp

        if (tid < 8) *(int*)(sm + RDY_OFF + tid * 4) = -1;
        __syncthreads();
        const uint32_t r_prev = sbase + RDY_OFF + (uint32_t)((w - 1) * 4);
        const uint32_t r_next = sbase + RDY_OFF + (uint32_t)((w + 1) * 4);
        const uint32_t r_self = sbase + RDY_OFF + (uint32_t)(w * 4);

        UC u;
        u.uf00 = uf[o];        u.uf01 = uf[128 + o];
        u.uf10 = uf[256 + o];  u.uf11 = uf[384 + o];
        u.ui0  = ui[o];        u.ui1  = ui[128 + o];
        u.uo0  = uo[o];        u.uo1  = uo[128 + o];
        u.uc0  = uc[o];        u.uc1  = uc[128 + o];

        const uint32_t* preb = g_pk + (size_t)b * NPW + o;
        float* outb = out + b * 128 + o;

        uint32_t buf[2][8][3];
        float sj[8], hj[8];
#pragma unroll
        for (int j = 0; j < 8; j++) { sj[j] = 0.f; hj[j] = 0.f; }

        // prologue: rows R8, R8+1 must be flagged before first prefetch
        waitflag(R8);
        waitflag(R8 + 1);
#pragma unroll
        for (int p = 0; p < 2; p++) {
#pragma unroll
            for (int j = 0; j < 8; j++) {
                int c = p - j; c = c < 0 ? 0 : c;
                const uint32_t* q = preb + (size_t)((R8 + j) * 64 + c) * WSTRIDE;
                buf[p][j][0] = ldg_plain(q);
                buf[p][j][1] = ldg_plain(q + 128);
                buf[p][j][2] = ldg_plain(q + 256);
            }
        }

#pragma unroll 1
        for (int s = 0; s <= 70; s++) {
            // flag-gate the row entering the prefetch window (row R8+s+2)
            if (s <= 5) waitflag(R8 + s + 2);

            float sup = 0.f, hup = 0.f;
            if (w > 0 && s <= 63) {
                SPIN_GE(r_prev, s + 7);
                int ps = (s + 7) & 3;
                sup = *(float*)(sm + SHS_OFF + (uint32_t)(((ps * 8 + (w - 1)) * 32 + lane) * 4));
                hup = *(float*)(sm + SHH_OFF + (uint32_t)(((ps * 8 + (w - 1)) * 32 + lane) * 4));
            }

            const int slot = s & 1;
            float up_s = sup, up_h = hup;
#pragma unroll
            for (int j = 0; j < 8; j++) {
                float o_s = sj[j], o_h = hj[j];
                int c = s - j;
                if (c >= 0 && c <= 63) {
                    float sv, hv;
                    cell_w(buf[slot][j], u, up_h, hj[j], up_s, sj[j], sv, hv);
                    outb[(size_t)((R8 + j) * 64 + c) * 4096] = sv;
                    sj[j] = sv; hj[j] = hv;
                }
                up_s = o_s; up_h = o_h;
            }

            // handoff row 7 -> warp w+1
            if (w < 7 && s >= 7 && s <= 70) {
                if (s >= 11) SPIN_GE(r_next, s - 11);
                int sl = s & 3;
                *(float*)(sm + SHS_OFF + (uint32_t)(((sl * 8 + w) * 32 + lane) * 4)) = sj[7];
                *(float*)(sm + SHH_OFF + (uint32_t)(((sl * 8 + w) * 32 + lane) * 4)) = hj[7];
            }

            __syncwarp();
            if (lane == 0) ST_REL(r_self, s);

            // refill slot for step s+2
#pragma unroll
            for (int j = 0; j < 8; j++) {
                int c = s + 2 - j;
                c = c < 0 ? 0 : (c > 63 ? 63 : c);
                const uint32_t* q = preb + (size_t)((R8 + j) * 64 + c) * WSTRIDE;
                buf[slot][j][0] = ldg_plain(q);
                buf[slot][j][1] = ldg_plain(q + 128);
                buf[slot][j][2] = ldg_plain(q + 256);
            }
        }
    } else {
        // ========================= GEMM =========================
        const int t  = blockIdx.x - 128;     // 0..2047, d1 = t>>5 ascending
        const int mb = t * 64;
        const int wm = w >> 2;               // 0..1 (32-row half)
        const int wn = w & 3;                // 0..3 (32-col quarter)

        // ---- load + convert X tile: 64 rows x 64 fp32 -> fp16 ----
        {
            const float4* X4 = (const float4*)(X + (size_t)mb * II);
#pragma unroll
            for (int it = 0; it < 4; it++) {
                int j = tid + it * 256;      // 1024 float4
                float4 v = X4[j];
                int row = j >> 4;
                int kq  = (j & 15) * 4;
                uint32_t off = (uint32_t)(row * (A_STR * 2) + kq * 2);
                *(uint2*)(sm + SM_A + off) =
                    make_uint2(h1(v.x) | (h1(v.y) << 16),
                               h1(v.z) | (h1(v.w) << 16));
            }
        }
        // ---- load + convert + transpose ALL gate weights ----
        {
            const int n    = tid & 127;
            const int half = tid >> 7;       // 0..1
#pragma unroll 1
            for (int g = 0; g < 5; g++) {
                const float* W;
                if (g == 0)      W = wf;
                else if (g == 1) W = wf + II * OO;
                else if (g == 2) W = wi;
                else if (g == 3) W = wo;
                else             W = wc;
                char* bh = sm + SM_B + g * 18432;
#pragma unroll
                for (int i = 0; i < 16; i++) {
                    int k0 = half * 32 + 2 * i;
                    float w0 = __ldg(W + (size_t)k0 * OO + n);
                    float w1 = __ldg(W + (size_t)(k0 + 1) * OO + n);
                    uint32_t off = (uint32_t)(n * (B_STR * 2) + k0 * 2);
                    *(uint32_t*)(bh + off) = h1(w0) | (h1(w1) << 16);
                }
            }
        }
        __syncthreads();

        const int lrow  = lane & 15;
        const int lcolb = (lane >> 4) * 16;
        uint32_t aAddr[2];
#pragma unroll
        for (int mi = 0; mi < 2; mi++) {
            uint32_t ro = (uint32_t)((wm * 32 + mi * 16 + lrow) * (A_STR * 2) + lcolb);
            aAddr[mi] = sbase + SM_A + ro;
        }
        uint32_t bAddr[2];
#pragma unroll
        for (int p = 0; p < 2; p++) {
            uint32_t ro = (uint32_t)((wn * 32 + p * 16 + lrow) * (B_STR * 2) + lcolb);
            bAddr[p] = sbase + SM_B + ro;
        }

        uint32_t aF[4][2][4];
#pragma unroll
        for (int ks = 0; ks < 4; ks++) {
            const uint32_t kb = (uint32_t)(ks * 32);
#pragma unroll
            for (int mi = 0; mi < 2; mi++)
                ldsm_x4(aF[ks][mi][0], aF[ks][mi][1], aF[ks][mi][2], aF[ks][mi][3],
                        aAddr[mi] + kb);
        }

        const int qr = lane >> 2;
        const int qc = (lane & 3) * 2;

#pragma unroll 1
        for (int pr = 0; pr < 3; pr++) {
            const int gA = 2 * pr;
            const bool hasB = (pr < 2);
            const float* biasA;
            const float* biasB = biasc;
            if (pr == 0)      { biasA = biasf; biasB = biasf + OO; }
            else if (pr == 1) { biasA = biasi; biasB = biaso;      }
            else              { biasA = biasc;                     }
            const uint32_t gAoff = (uint32_t)(gA * 18432);
            const uint32_t gBoff = gAoff + 18432;

            float accA[2][4][4], accB[2][4][4];
#pragma unroll
            for (int mi = 0; mi < 2; mi++)
#pragma unroll
                for (int ni = 0; ni < 4; ni++)
#pragma unroll
                    for (int e = 0; e < 4; e++) { accA[mi][ni][e] = 0.f; accB[mi][ni][e] = 0.f; }

#pragma unroll
            for (int ks = 0; ks < 4; ks++) {
                const uint32_t kb = (uint32_t)(ks * 32);
#pragma unroll
                for (int pq = 0; pq < 2; pq++) {
                    uint32_t b0, b1, b2, b3;
                    ldsm_x4(b0, b1, b2, b3, bAddr[pq] + gAoff + kb);
#pragma unroll
                    for (int mi = 0; mi < 2; mi++) {
                        mma_f16(accA[mi][2 * pq],     aF[ks][mi], b0, b2);
                        mma_f16(accA[mi][2 * pq + 1], aF[ks][mi], b1, b3);
                    }
                    if (hasB) {
                        uint32_t c0, c1, c2, c3;
                        ldsm_x4(c0, c1, c2, c3, bAddr[pq] + gBoff + kb);
#pragma unroll
                        for (int mi = 0; mi < 2; mi++) {
                            mma_f16(accB[mi][2 * pq],     aF[ks][mi], c0, c2);
                            mma_f16(accB[mi][2 * pq + 1], aF[ks][mi], c1, c3);
                        }
                    }
                }
            }

            // ---- epilogue: pack gate pair, uint2 stores (R7 layout) ----
#pragma unroll
            for (int ni = 0; ni < 4; ni++) {
                int col = wn * 32 + ni * 8 + qc;
                float bA0 = __ldg(biasA + col);
                float bA1 = __ldg(biasA + col + 1);
                float bB0 = hasB ? __ldg(biasB + col)     : 0.f;
                float bB1 = hasB ? __ldg(biasB + col + 1) : 0.f;
#pragma unroll
                for (int mi = 0; mi < 2; mi++) {
                    int row = mb + wm * 32 + mi * 16 + qr;
                    size_t idx = (size_t)row * NPW + (size_t)pr * 128 + col;
                    uint32_t w0, w1, w2, w3;
                    if (hasB) {
                        w0 = packh2(accA[mi][ni][0] + bA0, accB[mi][ni][0] + bB0);
                        w1 = packh2(accA[mi][ni][1] + bA1, accB[mi][ni][1] + bB1);
                        w2 = packh2(accA[mi][ni][2] + bA0, accB[mi][ni][2] + bB0);
                        w3 = packh2(accA[mi][ni][3] + bA1, accB[mi][ni][3] + bB1);
                    } else {
                        w0 = h1(accA[mi][ni][0] + bA0);
                        w1 = h1(accA[mi][ni][1] + bA1);
                        w2 = h1(accA[mi][ni][2] + bA0);
                        w3 = h1(accA[mi][ni][3] + bA1);
                    }
                    *(uint2*)(g_pk + idx) = make_uint2(w0, w1);
                    *(uint2*)(g_pk + idx + (size_t)8 * NPW) = make_uint2(w2, w3);
                }
            }
        }

        // ---- publish: all stores visible, then bump d1 counter ----
        __threadfence();
        __syncthreads();
        if (tid == 0) atomicAdd(&g_flags[mb >> 11], 1);
    }
}

// ================= launcher =================
extern "C" void kernel_launch(void* const* d_in, const int* in_sizes, int n_in,
                              void* d_out, int out_size) {
    (void)in_sizes; (void)n_in; (void)out_size;
    const float* x     = (const float*)d_in[0];
    const float* wf    = (const float*)d_in[1];
    const float* uf    = (const float*)d_in[2];
    const float* biasf = (const float*)d_in[3];
    const float* wi    = (const float*)d_in[4];
    const float* ui    = (const float*)d_in[5];
    const float* biasi = (const float*)d_in[6];
    const float* wo    = (const float*)d_in[7];
    const float* uo    = (const float*)d_in[8];
    const float* biaso = (const float*)d_in[9];
    const float* wc    = (const float*)d_in[10];
    const float* uc    = (const float*)d_in[11];
    const float* biasc = (const float*)d_in[12];
    float* out = (float*)d_out;

    init_flags<<<1, 64>>>();
    cudaFuncSetAttribute(mdlstm_combined,
                         cudaFuncAttributeMaxDynamicSharedMemorySize, SM_TOTAL);
    mdlstm_combined<<<2176, 256, SM_TOTAL>>>(
        x, wf, uf, biasf, wi, ui, biasi, wo, uo, biaso, wc, uc, biasc, out);
}

// round 14
// speedup vs baseline: 2.3355x; 2.3355x over previous
#include <cuda_runtime.h>
#include <cuda_fp16.h>
#include <cstdint>
#include <cstddef>

// Problem dims
#define D1 64
#define D2 64
#define BB 32
#define II 64
#define OO 128
#define M_TOT (D1 * D2 * BB)   // 131072

// Packed pre-activations: [cell m][word 0..319][...] uint32, word indexed by:
//   words 0..127   : (f0,f1) half2 for o = word
//   words 128..255 : (i,o)   half2 for o = word-128
//   words 256..319 : (c@2j, c@2j+1) half2, o reads word 256+(o>>1)
// Bias folded in.
#define NPW 320
#define CSTRIDE (32 * NPW)     // advance one grid position (fixed b) = 10240
__device__ uint32_t g_pk[(size_t)M_TOT * NPW];

// ========================= helpers =========================
__device__ __forceinline__ uint32_t smem_u32(const void* p) {
    uint32_t a;
    asm("{ .reg .u64 t; cvta.to.shared.u64 t, %1; cvt.u32.u64 %0, t; }"
        : "=r"(a) : "l"(p));
    return a;
}

__device__ __forceinline__ void ldsm_x4(uint32_t& r0, uint32_t& r1,
                                        uint32_t& r2, uint32_t& r3,
                                        uint32_t addr) {
    asm volatile("ldmatrix.sync.aligned.m8n8.x4.shared.b16 {%0,%1,%2,%3}, [%4];"
                 : "=r"(r0), "=r"(r1), "=r"(r2), "=r"(r3) : "r"(addr));
}

__device__ __forceinline__ void mma_f16(float* d, const uint32_t* a,
                                        uint32_t b0, uint32_t b1) {
    asm volatile(
        "mma.sync.aligned.m16n8k16.row.col.f32.f16.f16.f32 "
        "{%0,%1,%2,%3}, {%4,%5,%6,%7}, {%8,%9}, {%0,%1,%2,%3};"
        : "+f"(d[0]), "+f"(d[1]), "+f"(d[2]), "+f"(d[3])
        : "r"(a[0]), "r"(a[1]), "r"(a[2]), "r"(a[3]), "r"(b0), "r"(b1));
}

__device__ __forceinline__ uint32_t h1(float v) {
    __half h = __float2half_rn(v);
    return (uint32_t)(*reinterpret_cast<unsigned short*>(&h));
}
__device__ __forceinline__ uint32_t packh2(float a, float b) {
    __half2 h = __floats2half2_rn(a, b);
    return *reinterpret_cast<uint32_t*>(&h);
}
__device__ __forceinline__ float2 up2(uint32_t w) {
    __half2 h = *reinterpret_cast<__half2*>(&w);
    return __half22float2(h);
}

// ================= Kernel 1: HMMA fp16 (single-precision A) GEMM ===========
#define A_STR 72
#define B_STR 72

#define SM_A  0
#define SM_B  18432                       // + g*18432
#define SM_TOTAL (18432 * 6)              // 110592

__global__ void __launch_bounds__(512, 1) gemm_pre_hmma(
    const float* __restrict__ X,
    const float* __restrict__ wf, const float* __restrict__ wi,
    const float* __restrict__ wo, const float* __restrict__ wc,
    const float* __restrict__ biasf, const float* __restrict__ biasi,
    const float* __restrict__ biaso, const float* __restrict__ biasc)
{
    extern __shared__ __align__(1024) char sm[];
    const uint32_t sbase = smem_u32(sm);
    const int tid  = threadIdx.x;
    const int lane = tid & 31;
    const int w    = tid >> 5;
    const int wm   = w >> 2;
    const int wn   = w & 3;
    const int mb   = blockIdx.x * 128;

    // ---- load + convert X tile: 128 rows x 64 fp32 -> fp16 ----
    {
        const float4* X4 = (const float4*)(X + (size_t)mb * II);
#pragma unroll
        for (int it = 0; it < 4; it++) {
            int j = tid + it * 512;
            float4 v = X4[j];
            int row = j >> 4;
            int kq  = (j & 15) * 4;
            uint32_t off = (uint32_t)(row * (A_STR * 2) + kq * 2);
            *(uint2*)(sm + SM_A + off) =
                make_uint2(h1(v.x) | (h1(v.y) << 16), h1(v.z) | (h1(v.w) << 16));
        }
    }

    // ---- load + convert + transpose ALL gate weights -> Bsm[g][n][k] ----
    {
        const int n  = tid & 127;
        const int qu = tid >> 7;
#pragma unroll 1
        for (int g = 0; g < 5; g++) {
            const float* W;
            if (g == 0)      W = wf;
            else if (g == 1) W = wf + II * OO;
            else if (g == 2) W = wi;
            else if (g == 3) W = wo;
            else             W = wc;
            char* bh = sm + SM_B + g * 18432;
#pragma unroll
            for (int i = 0; i < 8; i++) {
                int k0 = qu * 16 + 2 * i;
                float w0 = __ldg(W + (size_t)k0 * OO + n);
                float w1 = __ldg(W + (size_t)(k0 + 1) * OO + n);
                uint32_t off = (uint32_t)(n * (B_STR * 2) + k0 * 2);
                *(uint32_t*)(bh + off) = h1(w0) | (h1(w1) << 16);
            }
        }
    }
    __syncthreads();

    const int lrow  = lane & 15;
    const int lcolb = (lane >> 4) * 16;
    uint32_t aAddr[2];
#pragma unroll
    for (int mi = 0; mi < 2; mi++) {
        uint32_t ro = (uint32_t)((wm * 32 + mi * 16 + lrow) * (A_STR * 2) + lcolb);
        aAddr[mi] = sbase + SM_A + ro;
    }
    uint32_t bAddr[2];
#pragma unroll
    for (int p = 0; p < 2; p++) {
        uint32_t ro = (uint32_t)((wn * 32 + p * 16 + lrow) * (B_STR * 2) + lcolb);
        bAddr[p] = sbase + SM_B + ro;
    }

    // A fragments hoisted (reused across gates)
    uint32_t aF[4][2][4];
#pragma unroll
    for (int ks = 0; ks < 4; ks++) {
        const uint32_t kb = (uint32_t)(ks * 32);
#pragma unroll
        for (int mi = 0; mi < 2; mi++)
            ldsm_x4(aF[ks][mi][0], aF[ks][mi][1], aF[ks][mi][2], aF[ks][mi][3],
                    aAddr[mi] + kb);
    }

    const int qr = lane >> 2;
    const int qc = (lane & 3) * 2;

    // ---- gate pairs: (0,1)->word0, (2,3)->word1, (4,-)->paired-c words ----
#pragma unroll 1
    for (int pr = 0; pr < 3; pr++) {
        const int gA = 2 * pr;
        const bool hasB = (pr < 2);
        const float* biasA;
        const float* biasB = biasc;
        if (pr == 0)      { biasA = biasf; biasB = biasf + OO; }
        else if (pr == 1) { biasA = biasi; biasB = biaso;      }
        else              { biasA = biasc;                     }
        const uint32_t gAoff = (uint32_t)(gA * 18432);
        const uint32_t gBoff = gAoff + 18432;

        float accA[2][4][4], accB[2][4][4];
#pragma unroll
        for (int mi = 0; mi < 2; mi++)
#pragma unroll
            for (int ni = 0; ni < 4; ni++)
#pragma unroll
                for (int e = 0; e < 4; e++) { accA[mi][ni][e] = 0.f; accB[mi][ni][e] = 0.f; }

#pragma unroll
        for (int ks = 0; ks < 4; ks++) {
            const uint32_t kb = (uint32_t)(ks * 32);
#pragma unroll
            for (int pq = 0; pq < 2; pq++) {
                uint32_t b0, b1, b2, b3;
                ldsm_x4(b0, b1, b2, b3, bAddr[pq] + gAoff + kb);
#pragma unroll
                for (int mi = 0; mi < 2; mi++) {
                    mma_f16(accA[mi][2 * pq],     aF[ks][mi], b0, b2);
                    mma_f16(accA[mi][2 * pq + 1], aF[ks][mi], b1, b3);
                }
                if (hasB) {
                    uint32_t c0, c1, c2, c3;
                    ldsm_x4(c0, c1, c2, c3, bAddr[pq] + gBoff + kb);
#pragma unroll
                    for (int mi = 0; mi < 2; mi++) {
                        mma_f16(accB[mi][2 * pq],     aF[ks][mi], c0, c2);
                        mma_f16(accB[mi][2 * pq + 1], aF[ks][mi], c1, c3);
                    }
                }
            }
        }

        // ---- epilogue ----
#pragma unroll
        for (int ni = 0; ni < 4; ni++) {
            int col = wn * 32 + ni * 8 + qc;
            float bA0 = __ldg(biasA + col);
            float bA1 = __ldg(biasA + col + 1);
            float bB0 = hasB ? __ldg(biasB + col)     : 0.f;
            float bB1 = hasB ? __ldg(biasB + col + 1) : 0.f;
#pragma unroll
            for (int mi = 0; mi < 2; mi++) {
                int row = mb + wm * 32 + mi * 16 + qr;
                if (hasB) {
                    size_t idx = (size_t)row * NPW + (size_t)pr * 128 + col;
                    uint32_t w0 = packh2(accA[mi][ni][0] + bA0, accB[mi][ni][0] + bB0);
                    uint32_t w1 = packh2(accA[mi][ni][1] + bA1, accB[mi][ni][1] + bB1);
                    uint32_t w2 = packh2(accA[mi][ni][2] + bA0, accB[mi][ni][2] + bB0);
                    uint32_t w3 = packh2(accA[mi][ni][3] + bA1, accB[mi][ni][3] + bB1);
                    *(uint2*)(g_pk + idx) = make_uint2(w0, w1);
                    *(uint2*)(g_pk + idx + (size_t)8 * NPW) = make_uint2(w2, w3);
                } else {
                    // paired-c: one word covers cols (col, col+1)
                    size_t idx = (size_t)row * NPW + 256 + (col >> 1);
                    uint32_t w0 = packh2(accA[mi][ni][0] + bA0, accA[mi][ni][1] + bA1);
                    uint32_t w1 = packh2(accA[mi][ni][2] + bA0, accA[mi][ni][3] + bA1);
                    g_pk[idx] = w0;
                    g_pk[idx + (size_t)8 * NPW] = w1;
                }
            }
        }
    }
}

// ================= Kernel 2: wavefront recurrence, 4 rows/warp, deep PF ====
__device__ __forceinline__ float sigf(float x) {
    float t;
    asm("tanh.approx.f32 %0, %1;" : "=f"(t) : "f"(0.5f * x));
    return fmaf(0.5f, t, 0.5f);
}
__device__ __forceinline__ float tanhapx(float x) {
    float y;
    asm("tanh.approx.f32 %0, %1;" : "=f"(y) : "f"(x));
    return y;
}

struct UC {
    float uf00, uf01, uf10, uf11;
    float ui0, ui1, uo0, uo1, uc0, uc1;
};

__device__ __forceinline__ void cell_w(const uint32_t qw[3], int lodd,
                                       const UC& u,
                                       float hup, float hl,
                                       float sup, float sl,
                                       float& s, float& h)
{
    float2 qa  = up2(qw[0]);   // (f0, f1)
    float2 qb  = up2(qw[1]);   // (i, o)
    float2 qcp = up2(qw[2]);   // (c_even, c_odd)
    float qcv = lodd ? qcp.y : qcp.x;
    float pf0 = fmaf(u.uf01, hl, fmaf(u.uf00, hup, qa.x));
    float pf1 = fmaf(u.uf11, hl, fmaf(u.uf10, hup, qa.y));
    float pi  = fmaf(u.ui1,  hl, fmaf(u.ui0,  hup, qb.x));
    float po  = fmaf(u.uo1,  hl, fmaf(u.uo0,  hup, qb.y));
    float pc  = fmaf(u.uc1,  hl, fmaf(u.uc0,  hup, qcv));
    float f0 = sigf(pf0);
    float f1 = sigf(pf1);
    float ig = sigf(pi);
    float og = sigf(po);
    float cg = sigf(pc);
    s = fmaf(f0, sup, fmaf(f1, sl, ig * cg));
    h = og * tanhapx(s);
}

// block = (b, o-group of 32). 16 warps; warp w owns rows 4w..4w+3; lane = o.
// Depth-4 register ring prefetch (R7 structure).
__global__ void __launch_bounds__(512, 1) mdlstm_rec_kernel(
    const float* __restrict__ uf, const float* __restrict__ ui,
    const float* __restrict__ uo, const float* __restrict__ uc,
    float* __restrict__ out)
{
    __shared__ float sh_s[4][16][32];
    __shared__ float sh_h[4][16][32];
    __shared__ int   ready[16];

    const int lane = threadIdx.x & 31;
    const int w    = threadIdx.x >> 5;     // 0..15
    const int b    = blockIdx.x >> 2;
    const int og   = blockIdx.x & 3;
    const int o    = og * 32 + lane;
    const int lodd = o & 1;

    if (threadIdx.x < 16) ready[threadIdx.x] = -1;
    __syncthreads();
    const uint32_t raddr  = smem_u32(ready);
    const uint32_t r_prev = raddr + 4u * (uint32_t)(w - 1);
    const uint32_t r_next = raddr + 4u * (uint32_t)(w + 1);
    const uint32_t r_self = raddr + 4u * (uint32_t)w;

    UC u;
    u.uf00 = uf[o];        u.uf01 = uf[128 + o];
    u.uf10 = uf[256 + o];  u.uf11 = uf[384 + o];
    u.ui0  = ui[o];        u.ui1  = ui[128 + o];
    u.uo0  = uo[o];        u.uo1  = uo[128 + o];
    u.uc0  = uc[o];        u.uc1  = uc[128 + o];

    const uint32_t* preb  = g_pk + (size_t)b * NPW + o;            // words 0/1
    const uint32_t* prebc = g_pk + (size_t)b * NPW + 256 + (o >> 1); // c word
    float* outb = out + b * 128 + o;

    // per-row col-0 bases
    const uint32_t* pbase[4];
    const uint32_t* pcbase[4];
    float* obase[4];
#pragma unroll
    for (int j = 0; j < 4; j++) {
        int r = 4 * w + j;
        pbase[j]  = preb  + (size_t)(r * 64) * CSTRIDE;
        pcbase[j] = prebc + (size_t)(r * 64) * CSTRIDE;
        obase[j]  = outb  + (size_t)(r * 64) * 4096;
    }

    // ring buffer: buf[slot][row][word]
    uint32_t buf[4][4][3];
#pragma unroll
    for (int p = 0; p < 4; p++) {
#pragma unroll
        for (int j = 0; j < 4; j++) {
            int col = p - j; col = col < 0 ? 0 : col;
            const uint32_t* q = pbase[j] + (size_t)col * CSTRIDE;
            buf[p][j][0] = __ldg(q);
            buf[p][j][1] = __ldg(q + 128);
            buf[p][j][2] = __ldg(pcbase[j] + (size_t)col * CSTRIDE);
        }
    }

    float sj[4] = {0.f, 0.f, 0.f, 0.f};
    float hj[4] = {0.f, 0.f, 0.f, 0.f};

#define REC_BODY(S, SLOT)                                                     \
    {                                                                         \
        const int s = (S);                                                    \
        float os0 = sj[0], oh0 = hj[0];                                       \
        float os1 = sj[1], oh1 = hj[1];                                       \
        float os2 = sj[2], oh2 = hj[2];                                       \
        /* row 0 */                                                           \
        if (s <= 63) {                                                        \
            float sup, hup;                                                   \
            if (w == 0) { sup = 0.f; hup = 0.f; }                             \
            else {                                                            \
                const int need = s + 3;                                       \
                int v;                                                        \
                do {                                                          \
                    asm volatile("ld.acquire.cta.shared.b32 %0, [%1];"        \
                                 : "=r"(v) : "r"(r_prev) : "memory");         \
                } while (v < need);                                           \
                sup = sh_s[(s + 3) & 3][w - 1][lane];                         \
                hup = sh_h[(s + 3) & 3][w - 1][lane];                         \
            }                                                                 \
            float sv, hv;                                                     \
            cell_w(buf[SLOT][0], lodd, u, hup, hj[0], sup, sj[0], sv, hv);    \
            obase[0][(size_t)s * 4096] = sv;                                  \
            sj[0] = sv; hj[0] = hv;                                           \
        }                                                                     \
        /* rows 1..3 */                                                       \
        if (s >= 1 && s <= 64) {                                              \
            float sv, hv;                                                     \
            cell_w(buf[SLOT][1], lodd, u, oh0, hj[1], os0, sj[1], sv, hv);    \
            obase[1][(size_t)(s - 1) * 4096] = sv;                            \
            sj[1] = sv; hj[1] = hv;                                           \
        }                                                                     \
        if (s >= 2 && s <= 65) {                                              \
            float sv, hv;                                                     \
            cell_w(buf[SLOT][2], lodd, u, oh1, hj[2], os1, sj[2], sv, hv);    \
            obase[2][(size_t)(s - 2) * 4096] = sv;                            \
            sj[2] = sv; hj[2] = hv;                                           \
        }                                                                     \
        if (s >= 3 && s <= 66) {                                              \
            float sv, hv;                                                     \
            cell_w(buf[SLOT][3], lodd, u, oh2, hj[3], os2, sj[3], sv, hv);    \
            obase[3][(size_t)(s - 3) * 4096] = sv;                            \
            sj[3] = sv; hj[3] = hv;                                           \
            if (w < 15) {                                                     \
                const int needc = s - 7;                                      \
                if (needc >= 0) {                                             \
                    int v;                                                    \
                    do {                                                      \
                        asm volatile("ld.acquire.cta.shared.b32 %0, [%1];"    \
                                     : "=r"(v) : "r"(r_next) : "memory");     \
                    } while (v < needc);                                      \
                }                                                             \
                sh_s[SLOT][w][lane] = sv;                                     \
                sh_h[SLOT][w][lane] = hv;                                     \
            }                                                                 \
        }                                                                     \
        if (lane == 0) {                                                      \
            asm volatile("st.release.cta.shared.b32 [%0], %1;"                \
                         :: "r"(r_self), "r"(s) : "memory");                  \
        }                                                                     \
        _Pragma("unroll")                                                     \
        for (int j = 0; j < 4; j++) {                                         \
            int col = s + 4 - j;                                              \
            col = col < 0 ? 0 : (col > 63 ? 63 : col);                        \
            const uint32_t* q = pbase[j] + (size_t)col * CSTRIDE;             \
            buf[SLOT][j][0] = __ldg(q);                                       \
            buf[SLOT][j][1] = __ldg(q + 128);                                 \
            buf[SLOT][j][2] = __ldg(pcbase[j] + (size_t)col * CSTRIDE);       \
        }                                                                     \
    }

#pragma unroll 1
    for (int sb = 0; sb < 68; sb += 4) {
        REC_BODY(sb + 0, 0)
        REC_BODY(sb + 1, 1)
        REC_BODY(sb + 2, 2)
        REC_BODY(sb + 3, 3)
    }
#undef REC_BODY
}

// ================= launcher =================
extern "C" void kernel_launch(void* const* d_in, const int* in_sizes, int n_in,
                              void* d_out, int out_size) {
    (void)in_sizes; (void)n_in; (void)out_size;
    const float* x     = (const float*)d_in[0];
    const float* wf    = (const float*)d_in[1];
    const float* uf    = (const float*)d_in[2];
    const float* biasf = (const float*)d_in[3];
    const float* wi    = (const float*)d_in[4];
    const float* ui    = (const float*)d_in[5];
    const float* biasi = (const float*)d_in[6];
    const float* wo    = (const float*)d_in[7];
    const float* uo    = (const float*)d_in[8];
    const float* biaso = (const float*)d_in[9];
    const float* wc    = (const float*)d_in[10];
    const float* uc    = (const float*)d_in[11];
    const float* biasc = (const float*)d_in[12];
    float* out = (float*)d_out;

    cudaFuncSetAttribute(gemm_pre_hmma,
                         cudaFuncAttributeMaxDynamicSharedMemorySize, SM_TOTAL);
    gemm_pre_hmma<<<1024, 512, SM_TOTAL>>>(
        x, wf, wi, wo, wc, biasf, biasi, biaso, biasc);
    mdlstm_rec_kernel<<<128, 512>>>(uf, ui, uo, uc, out);
}

// round 15
// speedup vs baseline: 2.4392x; 1.0444x over previous
#include <cuda_runtime.h>
#include <cuda_fp16.h>
#include <cstdint>
#include <cstddef>

// Problem dims
#define D1 64
#define D2 64
#define BB 32
#define II 64
#define OO 128
#define M_TOT (D1 * D2 * BB)   // 131072

// Packed pre-activations (R7 layout): [cell m][word p=0..2][o=0..127] uint32.
// word0 = (f0,f1), word1 = (i,o), word2 = (c,pad). Bias folded in.
#define NPW 384
#define CSTRIDE (32 * NPW)     // advance one grid position (fixed b) = 12288
__device__ uint32_t g_pk[(size_t)M_TOT * NPW];

// ========================= helpers =========================
__device__ __forceinline__ uint32_t smem_u32(const void* p) {
    uint32_t a;
    asm("{ .reg .u64 t; cvta.to.shared.u64 t, %1; cvt.u32.u64 %0, t; }"
        : "=r"(a) : "l"(p));
    return a;
}

__device__ __forceinline__ void ldsm_x4(uint32_t& r0, uint32_t& r1,
                                        uint32_t& r2, uint32_t& r3,
                                        uint32_t addr) {
    asm volatile("ldmatrix.sync.aligned.m8n8.x4.shared.b16 {%0,%1,%2,%3}, [%4];"
                 : "=r"(r0), "=r"(r1), "=r"(r2), "=r"(r3) : "r"(addr));
}

__device__ __forceinline__ void mma_f16(float* d, const uint32_t* a,
                                        uint32_t b0, uint32_t b1) {
    asm volatile(
        "mma.sync.aligned.m16n8k16.row.col.f32.f16.f16.f32 "
        "{%0,%1,%2,%3}, {%4,%5,%6,%7}, {%8,%9}, {%0,%1,%2,%3};"
        : "+f"(d[0]), "+f"(d[1]), "+f"(d[2]), "+f"(d[3])
        : "r"(a[0]), "r"(a[1]), "r"(a[2]), "r"(a[3]), "r"(b0), "r"(b1));
}

__device__ __forceinline__ uint32_t h1(float v) {
    __half h = __float2half_rn(v);
    return (uint32_t)(*reinterpret_cast<unsigned short*>(&h));
}
__device__ __forceinline__ uint32_t packh2(float a, float b) {
    __half2 h = __floats2half2_rn(a, b);
    return *reinterpret_cast<uint32_t*>(&h);
}
__device__ __forceinline__ float2 up2(uint32_t w) {
    __half2 h = *reinterpret_cast<__half2*>(&w);
    return __half22float2(h);
}

// ================= Kernel 1: HMMA fp16 GEMM, 2 m-tiles per block ===========
// Block loads W once + BOTH X tiles (double-buffered A), one barrier, then
// computes two 128-row tiles back-to-back with no further syncs.
#define A_STR 72
#define B_STR 72

#define SM_A0 0
#define SM_A1 18432
#define SM_B  36864                       // + g*18432
#define SM_TOTAL (36864 + 5 * 18432)      // 129024

__global__ void __launch_bounds__(512, 1) gemm_pre_hmma(
    const float* __restrict__ X,
    const float* __restrict__ wf, const float* __restrict__ wi,
    const float* __restrict__ wo, const float* __restrict__ wc,
    const float* __restrict__ biasf, const float* __restrict__ biasi,
    const float* __restrict__ biaso, const float* __restrict__ biasc)
{
    extern __shared__ __align__(1024) char sm[];
    const uint32_t sbase = smem_u32(sm);
    const int tid  = threadIdx.x;
    const int lane = tid & 31;
    const int w    = tid >> 5;
    const int wm   = w >> 2;
    const int wn   = w & 3;
    const int mb0  = blockIdx.x * 256;

    // ---- load + convert BOTH X tiles: 256 rows x 64 fp32 -> fp16 ----
    {
        const float4* X4 = (const float4*)(X + (size_t)mb0 * II);
#pragma unroll
        for (int it = 0; it < 8; it++) {
            int j = tid + it * 512;          // 4096 float4 total
            float4 v = X4[j];
            int row = j >> 4;                // 0..255
            int kq  = (j & 15) * 4;
            int buf = (row >= 128);
            int r   = row & 127;
            uint32_t off = (uint32_t)(buf ? SM_A1 : SM_A0)
                         + (uint32_t)(r * (A_STR * 2) + kq * 2);
            *(uint2*)(sm + off) =
                make_uint2(h1(v.x) | (h1(v.y) << 16), h1(v.z) | (h1(v.w) << 16));
        }
    }

    // ---- load + convert + transpose ALL gate weights -> Bsm[g][n][k] ----
    {
        const int n  = tid & 127;
        const int qu = tid >> 7;
#pragma unroll 1
        for (int g = 0; g < 5; g++) {
            const float* W;
            if (g == 0)      W = wf;
            else if (g == 1) W = wf + II * OO;
            else if (g == 2) W = wi;
            else if (g == 3) W = wo;
            else             W = wc;
            char* bh = sm + SM_B + g * 18432;
#pragma unroll
            for (int i = 0; i < 8; i++) {
                int k0 = qu * 16 + 2 * i;
                float w0 = __ldg(W + (size_t)k0 * OO + n);
                float w1 = __ldg(W + (size_t)(k0 + 1) * OO + n);
                uint32_t off = (uint32_t)(n * (B_STR * 2) + k0 * 2);
                *(uint32_t*)(bh + off) = h1(w0) | (h1(w1) << 16);
            }
        }
    }
    __syncthreads();   // the ONLY block barrier

    const int lrow  = lane & 15;
    const int lcolb = (lane >> 4) * 16;
    const uint32_t aRowOff =
        (uint32_t)((wm * 32 + lrow) * (A_STR * 2) + lcolb);
    uint32_t bAddr[2];
#pragma unroll
    for (int p = 0; p < 2; p++) {
        uint32_t ro = (uint32_t)((wn * 32 + p * 16 + lrow) * (B_STR * 2) + lcolb);
        bAddr[p] = sbase + SM_B + ro;
    }

    const int qr = lane >> 2;
    const int qc = (lane & 3) * 2;

#pragma unroll 1
    for (int t2 = 0; t2 < 2; t2++) {
        const int mb = mb0 + t2 * 128;
        const uint32_t aBase = sbase + (t2 ? SM_A1 : SM_A0) + aRowOff;

        // A fragments hoisted (reused across all 5 gates)
        uint32_t aF[4][2][4];
#pragma unroll
        for (int ks = 0; ks < 4; ks++) {
            const uint32_t kb = (uint32_t)(ks * 32);
#pragma unroll
            for (int mi = 0; mi < 2; mi++)
                ldsm_x4(aF[ks][mi][0], aF[ks][mi][1], aF[ks][mi][2], aF[ks][mi][3],
                        aBase + (uint32_t)(mi * 16 * (A_STR * 2)) + kb);
        }

        // ---- gate pairs: (0,1), (2,3), (4,-) ----
#pragma unroll 1
        for (int pr = 0; pr < 3; pr++) {
            const int gA = 2 * pr;
            const bool hasB = (pr < 2);
            const float* biasA;
            const float* biasB = biasc;
            if (pr == 0)      { biasA = biasf; biasB = biasf + OO; }
            else if (pr == 1) { biasA = biasi; biasB = biaso;      }
            else              { biasA = biasc;                     }
            const uint32_t gAoff = (uint32_t)(gA * 18432);
            const uint32_t gBoff = gAoff + 18432;

            float accA[2][4][4], accB[2][4][4];
#pragma unroll
            for (int mi = 0; mi < 2; mi++)
#pragma unroll
                for (int ni = 0; ni < 4; ni++)
#pragma unroll
                    for (int e = 0; e < 4; e++) { accA[mi][ni][e] = 0.f; accB[mi][ni][e] = 0.f; }

#pragma unroll
            for (int ks = 0; ks < 4; ks++) {
                const uint32_t kb = (uint32_t)(ks * 32);
#pragma unroll
                for (int pq = 0; pq < 2; pq++) {
                    uint32_t b0, b1, b2, b3;
                    ldsm_x4(b0, b1, b2, b3, bAddr[pq] + gAoff + kb);
#pragma unroll
                    for (int mi = 0; mi < 2; mi++) {
                        mma_f16(accA[mi][2 * pq],     aF[ks][mi], b0, b2);
                        mma_f16(accA[mi][2 * pq + 1], aF[ks][mi], b1, b3);
                    }
                    if (hasB) {
                        uint32_t c0, c1, c2, c3;
                        ldsm_x4(c0, c1, c2, c3, bAddr[pq] + gBoff + kb);
#pragma unroll
                        for (int mi = 0; mi < 2; mi++) {
                            mma_f16(accB[mi][2 * pq],     aF[ks][mi], c0, c2);
                            mma_f16(accB[mi][2 * pq + 1], aF[ks][mi], c1, c3);
                        }
                    }
                }
            }

            // ---- epilogue: pack two gates into one uint32 word, uint2 stores ----
#pragma unroll
            for (int ni = 0; ni < 4; ni++) {
                int col = wn * 32 + ni * 8 + qc;
                float bA0 = __ldg(biasA + col);
                float bA1 = __ldg(biasA + col + 1);
                float bB0 = hasB ? __ldg(biasB + col)     : 0.f;
                float bB1 = hasB ? __ldg(biasB + col + 1) : 0.f;
#pragma unroll
                for (int mi = 0; mi < 2; mi++) {
                    int row = mb + wm * 32 + mi * 16 + qr;
                    size_t idx = (size_t)row * NPW + (size_t)pr * 128 + col;
                    uint32_t w0, w1, w2, w3;
                    if (hasB) {
                        w0 = packh2(accA[mi][ni][0] + bA0, accB[mi][ni][0] + bB0);
                        w1 = packh2(accA[mi][ni][1] + bA1, accB[mi][ni][1] + bB1);
                        w2 = packh2(accA[mi][ni][2] + bA0, accB[mi][ni][2] + bB0);
                        w3 = packh2(accA[mi][ni][3] + bA1, accB[mi][ni][3] + bB1);
                    } else {
                        w0 = h1(accA[mi][ni][0] + bA0);
                        w1 = h1(accA[mi][ni][1] + bA1);
                        w2 = h1(accA[mi][ni][2] + bA0);
                        w3 = h1(accA[mi][ni][3] + bA1);
                    }
                    *(uint2*)(g_pk + idx) = make_uint2(w0, w1);
                    *(uint2*)(g_pk + idx + (size_t)8 * NPW) = make_uint2(w2, w3);
                }
            }
        }
    }
}

// ================= Kernel 2: wavefront recurrence (EXACT R7) ==============
__device__ __forceinline__ float sigf(float x) {
    float t;
    asm("tanh.approx.f32 %0, %1;" : "=f"(t) : "f"(0.5f * x));
    return fmaf(0.5f, t, 0.5f);
}
__device__ __forceinline__ float tanhapx(float x) {
    float y;
    asm("tanh.approx.f32 %0, %1;" : "=f"(y) : "f"(x));
    return y;
}

struct UC {
    float uf00, uf01, uf10, uf11;
    float ui0, ui1, uo0, uo1, uc0, uc1;
};

__device__ __forceinline__ void cell_w(const uint32_t qw[3], const UC& u,
                                       float hup, float hl,
                                       float sup, float sl,
                                       float& s, float& h)
{
    float2 qa = up2(qw[0]);   // (f0, f1)
    float2 qb = up2(qw[1]);   // (i, o)
    float2 qcv = up2(qw[2]);  // (c, pad)
    float pf0 = fmaf(u.uf01, hl, fmaf(u.uf00, hup, qa.x));
    float pf1 = fmaf(u.uf11, hl, fmaf(u.uf10, hup, qa.y));
    float pi  = fmaf(u.ui1,  hl, fmaf(u.ui0,  hup, qb.x));
    float po  = fmaf(u.uo1,  hl, fmaf(u.uo0,  hup, qb.y));
    float pc  = fmaf(u.uc1,  hl, fmaf(u.uc0,  hup, qcv.x));
    float f0 = sigf(pf0);
    float f1 = sigf(pf1);
    float ig = sigf(pi);
    float og = sigf(po);
    float cg = sigf(pc);
    s = fmaf(f0, sup, fmaf(f1, sl, ig * cg));
    h = og * tanhapx(s);
}

// block = (b, o-group of 32). 16 warps; warp w owns rows 4w..4w+3; lane = o.
__global__ void __launch_bounds__(512, 1) mdlstm_rec_kernel(
    const float* __restrict__ uf, const float* __restrict__ ui,
    const float* __restrict__ uo, const float* __restrict__ uc,
    float* __restrict__ out)
{
    __shared__ float sh_s[4][16][32];
    __shared__ float sh_h[4][16][32];
    __shared__ int   ready[16];

    const int lane = threadIdx.x & 31;
    const int w    = threadIdx.x >> 5;     // 0..15
    const int b    = blockIdx.x >> 2;
    const int og   = blockIdx.x & 3;
    const int o    = og * 32 + lane;

    if (threadIdx.x < 16) ready[threadIdx.x] = -1;
    __syncthreads();
    const uint32_t raddr  = smem_u32(ready);
    const uint32_t r_prev = raddr + 4u * (uint32_t)(w - 1);
    const uint32_t r_next = raddr + 4u * (uint32_t)(w + 1);
    const uint32_t r_self = raddr + 4u * (uint32_t)w;

    UC u;
    u.uf00 = uf[o];        u.uf01 = uf[128 + o];
    u.uf10 = uf[256 + o];  u.uf11 = uf[384 + o];
    u.ui0  = ui[o];        u.ui1  = ui[128 + o];
    u.uo0  = uo[o];        u.uo1  = uo[128 + o];
    u.uc0  = uc[o];        u.uc1  = uc[128 + o];

    const uint32_t* preb = g_pk + (size_t)b * NPW + o;
    float* outb = out + b * 128 + o;

    const uint32_t* pbase[4];
    float* obase[4];
#pragma unroll
    for (int j = 0; j < 4; j++) {
        int r = 4 * w + j;
        pbase[j] = preb + (size_t)(r * 64) * CSTRIDE;
        obase[j] = outb + (size_t)(r * 64) * 4096;
    }

    uint32_t buf[4][4][3];
#pragma unroll
    for (int p = 0; p < 4; p++) {
#pragma unroll
        for (int j = 0; j < 4; j++) {
            int col = p - j; col = col < 0 ? 0 : col;
            const uint32_t* q = pbase[j] + (size_t)col * CSTRIDE;
            buf[p][j][0] = __ldg(q);
            buf[p][j][1] = __ldg(q + 128);
            buf[p][j][2] = __ldg(q + 256);
        }
    }

    float sj[4] = {0.f, 0.f, 0.f, 0.f};
    float hj[4] = {0.f, 0.f, 0.f, 0.f};

#define REC_BODY(S, SLOT)                                                     \
    {                                                                         \
        const int s = (S);                                                    \
        float os0 = sj[0], oh0 = hj[0];                                       \
        float os1 = sj[1], oh1 = hj[1];                                       \
        float os2 = sj[2], oh2 = hj[2];                                       \
        /* row 0 */                                                           \
        if (s <= 63) {                                                        \
            float sup, hup;                                                   \
            if (w == 0) { sup = 0.f; hup = 0.f; }                             \
            else {                                                            \
                const int need = s + 3;                                       \
                int v;                                                        \
                do {                                                          \
                    asm volatile("ld.acquire.cta.shared.b32 %0, [%1];"        \
                                 : "=r"(v) : "r"(r_prev) : "memory");         \
                } while (v < need);                                           \
                sup = sh_s[(s + 3) & 3][w - 1][lane];                         \
                hup = sh_h[(s + 3) & 3][w - 1][lane];                         \
            }                                                                 \
            float sv, hv;                                                     \
            cell_w(buf[SLOT][0], u, hup, hj[0], sup, sj[0], sv, hv);          \
            obase[0][(size_t)s * 4096] = sv;                                  \
            sj[0] = sv; hj[0] = hv;                                           \
        }                                                                     \
        /* rows 1..3 */                                                       \
        if (s >= 1 && s <= 64) {                                              \
            float sv, hv;                                                     \
            cell_w(buf[SLOT][1], u, oh0, hj[1], os0, sj[1], sv, hv);          \
            obase[1][(size_t)(s - 1) * 4096] = sv;                            \
            sj[1] = sv; hj[1] = hv;                                           \
        }                                                                     \
        if (s >= 2 && s <= 65) {                                              \
            float sv, hv;                                                     \
            cell_w(buf[SLOT][2], u, oh1, hj[2], os1, sj[2], sv, hv);          \
            obase[2][(size_t)(s - 2) * 4096] = sv;                            \
            sj[2] = sv; hj[2] = hv;                                           \
        }                                                                     \
        if (s >= 3 && s <= 66) {                                              \
            float sv, hv;                                                     \
            cell_w(buf[SLOT][3], u, oh2, hj[3], os2, sj[3], sv, hv);          \
            obase[3][(size_t)(s - 3) * 4096] = sv;                            \
            sj[3] = sv; hj[3] = hv;                                           \
            if (w < 15) {                                                     \
                const int needc = s - 7;                                      \
                if (needc >= 0) {                                             \
                    int v;                                                    \
                    do {                                                      \
                        asm volatile("ld.acquire.cta.shared.b32 %0, [%1];"    \
                                     : "=r"(v) : "r"(r_next) : "memory");     \
                    } while (v < needc);                                      \
                }                                                             \
                sh_s[SLOT][w][lane] = sv;                                     \
                sh_h[SLOT][w][lane] = hv;                                     \
            }                                                                 \
        }                                                                     \
        if (lane == 0) {                                                      \
            asm volatile("st.release.cta.shared.b32 [%0], %1;"                \
                         :: "r"(r_self), "r"(s) : "memory");                  \
        }                                                                     \
        _Pragma("unroll")                                                     \
        for (int j = 0; j < 4; j++) {                                         \
            int col = s + 4 - j;                                              \
            col = col < 0 ? 0 : (col > 63 ? 63 : col);                        \
            const uint32_t* q = pbase[j] + (size_t)col * CSTRIDE;             \
            buf[SLOT][j][0] = __ldg(q);                                       \
            buf[SLOT][j][1] = __ldg(q + 128);                                 \
            buf[SLOT][j][2] = __ldg(q + 256);                                 \
        }                                                                     \
    }

#pragma unroll 1
    for (int sb = 0; sb < 68; sb += 4) {
        REC_BODY(sb + 0, 0)
        REC_BODY(sb + 1, 1)
        REC_BODY(sb + 2, 2)
        REC_BODY(sb + 3, 3)
    }
#undef REC_BODY
}

// ================= launcher =================
extern "C" void kernel_launch(void* const* d_in, const int* in_sizes, int n_in,
                              void* d_out, int out_size) {
    (void)in_sizes; (void)n_in; (void)out_size;
    const float* x     = (const float*)d_in[0];
    const float* wf    = (const float*)d_in[1];
    const float* uf    = (const float*)d_in[2];
    const float* biasf = (const float*)d_in[3];
    const float* wi    = (const float*)d_in[4];
    const float* ui    = (const float*)d_in[5];
    const float* biasi = (const float*)d_in[6];
    const float* wo    = (const float*)d_in[7];
    const float* uo    = (const float*)d_in[8];
    const float* biaso = (const float*)d_in[9];
    const float* wc    = (const float*)d_in[10];
    const float* uc    = (const float*)d_in[11];
    const float* biasc = (const float*)d_in[12];
    float* out = (float*)d_out;

    cudaFuncSetAttribute(gemm_pre_hmma,
                         cudaFuncAttributeMaxDynamicSharedMemorySize, SM_TOTAL);
    gemm_pre_hmma<<<512, 512, SM_TOTAL>>>(
        x, wf, wi, wo, wc, biasf, biasi, biaso, biasc);
    mdlstm_rec_kernel<<<128, 512>>>(uf, ui, uo, uc, out);
}

// round 16
// speedup vs baseline: 2.4428x; 1.0015x over previous
#include <cuda_runtime.h>
#include <cuda_fp16.h>
#include <cstdint>
#include <cstddef>

// Problem dims
#define D1 64
#define D2 64
#define BB 32
#define II 64
#define OO 128
#define M_TOT (D1 * D2 * BB)   // 131072

// Packed pre-activations (R7 layout): [cell m][word p=0..2][o=0..127] uint32.
// word0 = (f0,f1), word1 = (i,o), word2 = (c,pad). Bias folded in.
#define NPW 384
#define CSTRIDE (32 * NPW)     // advance one grid position (fixed b) = 12288
__device__ uint32_t g_pk[(size_t)M_TOT * NPW];

// ========================= helpers =========================
__device__ __forceinline__ uint32_t smem_u32(const void* p) {
    uint32_t a;
    asm("{ .reg .u64 t; cvta.to.shared.u64 t, %1; cvt.u32.u64 %0, t; }"
        : "=r"(a) : "l"(p));
    return a;
}

__device__ __forceinline__ void ldsm_x4(uint32_t& r0, uint32_t& r1,
                                        uint32_t& r2, uint32_t& r3,
                                        uint32_t addr) {
    asm volatile("ldmatrix.sync.aligned.m8n8.x4.shared.b16 {%0,%1,%2,%3}, [%4];"
                 : "=r"(r0), "=r"(r1), "=r"(r2), "=r"(r3) : "r"(addr));
}

__device__ __forceinline__ void mma_f16(float* d, const uint32_t* a,
                                        uint32_t b0, uint32_t b1) {
    asm volatile(
        "mma.sync.aligned.m16n8k16.row.col.f32.f16.f16.f32 "
        "{%0,%1,%2,%3}, {%4,%5,%6,%7}, {%8,%9}, {%0,%1,%2,%3};"
        : "+f"(d[0]), "+f"(d[1]), "+f"(d[2]), "+f"(d[3])
        : "r"(a[0]), "r"(a[1]), "r"(a[2]), "r"(a[3]), "r"(b0), "r"(b1));
}

__device__ __forceinline__ uint32_t h1(float v) {
    __half h = __float2half_rn(v);
    return (uint32_t)(*reinterpret_cast<unsigned short*>(&h));
}
__device__ __forceinline__ uint32_t packh2(float a, float b) {
    __half2 h = __floats2half2_rn(a, b);
    return *reinterpret_cast<uint32_t*>(&h);
}
__device__ __forceinline__ float2 up2(uint32_t w) {
    __half2 h = *reinterpret_cast<__half2*>(&w);
    return __half22float2(h);
}

// ================= Kernel 1: HMMA fp16 GEMM, 2 m-tiles per block ===========
// Block loads W once + BOTH X tiles (double-buffered A), one barrier, then
// computes two 128-row tiles back-to-back with no further syncs.
#define A_STR 72
#define B_STR 72

#define SM_A0 0
#define SM_A1 18432
#define SM_B  36864                       // + g*18432
#define SM_TOTAL (36864 + 5 * 18432)      // 129024

__global__ void __launch_bounds__(512, 1) gemm_pre_hmma(
    const float* __restrict__ X,
    const float* __restrict__ wf, const float* __restrict__ wi,
    const float* __restrict__ wo, const float* __restrict__ wc,
    const float* __restrict__ biasf, const float* __restrict__ biasi,
    const float* __restrict__ biaso, const float* __restrict__ biasc)
{
    extern __shared__ __align__(1024) char sm[];
    const uint32_t sbase = smem_u32(sm);
    const int tid  = threadIdx.x;
    const int lane = tid & 31;
    const int w    = tid >> 5;
    const int wm   = w >> 2;
    const int wn   = w & 3;
    const int mb0  = blockIdx.x * 256;

    // ---- load + convert BOTH X tiles: 256 rows x 64 fp32 -> fp16 ----
    {
        const float4* X4 = (const float4*)(X + (size_t)mb0 * II);
#pragma unroll
        for (int it = 0; it < 8; it++) {
            int j = tid + it * 512;          // 4096 float4 total
            float4 v = X4[j];
            int row = j >> 4;                // 0..255
            int kq  = (j & 15) * 4;
            int buf = (row >= 128);
            int r   = row & 127;
            uint32_t off = (uint32_t)(buf ? SM_A1 : SM_A0)
                         + (uint32_t)(r * (A_STR * 2) + kq * 2);
            *(uint2*)(sm + off) =
                make_uint2(h1(v.x) | (h1(v.y) << 16), h1(v.z) | (h1(v.w) << 16));
        }
    }

    // ---- load + convert + transpose ALL gate weights -> Bsm[g][n][k] ----
    {
        const int n  = tid & 127;
        const int qu = tid >> 7;
#pragma unroll 1
        for (int g = 0; g < 5; g++) {
            const float* W;
            if (g == 0)      W = wf;
            else if (g == 1) W = wf + II * OO;
            else if (g == 2) W = wi;
            else if (g == 3) W = wo;
            else             W = wc;
            char* bh = sm + SM_B + g * 18432;
#pragma unroll
            for (int i = 0; i < 8; i++) {
                int k0 = qu * 16 + 2 * i;
                float w0 = __ldg(W + (size_t)k0 * OO + n);
                float w1 = __ldg(W + (size_t)(k0 + 1) * OO + n);
                uint32_t off = (uint32_t)(n * (B_STR * 2) + k0 * 2);
                *(uint32_t*)(bh + off) = h1(w0) | (h1(w1) << 16);
            }
        }
    }
    __syncthreads();   // the ONLY block barrier

    const int lrow  = lane & 15;
    const int lcolb = (lane >> 4) * 16;
    const uint32_t aRowOff =
        (uint32_t)((wm * 32 + lrow) * (A_STR * 2) + lcolb);
    uint32_t bAddr[2];
#pragma unroll
    for (int p = 0; p < 2; p++) {
        uint32_t ro = (uint32_t)((wn * 32 + p * 16 + lrow) * (B_STR * 2) + lcolb);
        bAddr[p] = sbase + SM_B + ro;
    }

    const int qr = lane >> 2;
    const int qc = (lane & 3) * 2;

#pragma unroll 1
    for (int t2 = 0; t2 < 2; t2++) {
        const int mb = mb0 + t2 * 128;
        const uint32_t aBase = sbase + (t2 ? SM_A1 : SM_A0) + aRowOff;

        // A fragments hoisted (reused across all 5 gates)
        uint32_t aF[4][2][4];
#pragma unroll
        for (int ks = 0; ks < 4; ks++) {
            const uint32_t kb = (uint32_t)(ks * 32);
#pragma unroll
            for (int mi = 0; mi < 2; mi++)
                ldsm_x4(aF[ks][mi][0], aF[ks][mi][1], aF[ks][mi][2], aF[ks][mi][3],
                        aBase + (uint32_t)(mi * 16 * (A_STR * 2)) + kb);
        }

        // ---- gate pairs: (0,1), (2,3), (4,-) ----
#pragma unroll 1
        for (int pr = 0; pr < 3; pr++) {
            const int gA = 2 * pr;
            const bool hasB = (pr < 2);
            const float* biasA;
            const float* biasB = biasc;
            if (pr == 0)      { biasA = biasf; biasB = biasf + OO; }
            else if (pr == 1) { biasA = biasi; biasB = biaso;      }
            else              { biasA = biasc;                     }
            const uint32_t gAoff = (uint32_t)(gA * 18432);
            const uint32_t gBoff = gAoff + 18432;

            float accA[2][4][4], accB[2][4][4];
#pragma unroll
            for (int mi = 0; mi < 2; mi++)
#pragma unroll
                for (int ni = 0; ni < 4; ni++)
#pragma unroll
                    for (int e = 0; e < 4; e++) { accA[mi][ni][e] = 0.f; accB[mi][ni][e] = 0.f; }

#pragma unroll
            for (int ks = 0; ks < 4; ks++) {
                const uint32_t kb = (uint32_t)(ks * 32);
#pragma unroll
                for (int pq = 0; pq < 2; pq++) {
                    uint32_t b0, b1, b2, b3;
                    ldsm_x4(b0, b1, b2, b3, bAddr[pq] + gAoff + kb);
#pragma unroll
                    for (int mi = 0; mi < 2; mi++) {
                        mma_f16(accA[mi][2 * pq],     aF[ks][mi], b0, b2);
                        mma_f16(accA[mi][2 * pq + 1], aF[ks][mi], b1, b3);
                    }
                    if (hasB) {
                        uint32_t c0, c1, c2, c3;
                        ldsm_x4(c0, c1, c2, c3, bAddr[pq] + gBoff + kb);
#pragma unroll
                        for (int mi = 0; mi < 2; mi++) {
                            mma_f16(accB[mi][2 * pq],     aF[ks][mi], c0, c2);
                            mma_f16(accB[mi][2 * pq + 1], aF[ks][mi], c1, c3);
                        }
                    }
                }
            }

            // ---- epilogue: pack two gates into one uint32 word, uint2 stores ----
#pragma unroll
            for (int ni = 0; ni < 4; ni++) {
                int col = wn * 32 + ni * 8 + qc;
                float bA0 = __ldg(biasA + col);
                float bA1 = __ldg(biasA + col + 1);
                float bB0 = hasB ? __ldg(biasB + col)     : 0.f;
                float bB1 = hasB ? __ldg(biasB + col + 1) : 0.f;
#pragma unroll
                for (int mi = 0; mi < 2; mi++) {
                    int row = mb + wm * 32 + mi * 16 + qr;
                    size_t idx = (size_t)row * NPW + (size_t)pr * 128 + col;
                    uint32_t w0, w1, w2, w3;
                    if (hasB) {
                        w0 = packh2(accA[mi][ni][0] + bA0, accB[mi][ni][0] + bB0);
                        w1 = packh2(accA[mi][ni][1] + bA1, accB[mi][ni][1] + bB1);
                        w2 = packh2(accA[mi][ni][2] + bA0, accB[mi][ni][2] + bB0);
                        w3 = packh2(accA[mi][ni][3] + bA1, accB[mi][ni][3] + bB1);
                    } else {
                        w0 = h1(accA[mi][ni][0] + bA0);
                        w1 = h1(accA[mi][ni][1] + bA1);
                        w2 = h1(accA[mi][ni][2] + bA0);
                        w3 = h1(accA[mi][ni][3] + bA1);
                    }
                    *(uint2*)(g_pk + idx) = make_uint2(w0, w1);
                    *(uint2*)(g_pk + idx + (size_t)8 * NPW) = make_uint2(w2, w3);
                }
            }
        }
    }
}

// ================= Kernel 2: wavefront recurrence (EXACT R7) ==============
__device__ __forceinline__ float sigf(float x) {
    float t;
    asm("tanh.approx.f32 %0, %1;" : "=f"(t) : "f"(0.5f * x));
    return fmaf(0.5f, t, 0.5f);
}
__device__ __forceinline__ float tanhapx(float x) {
    float y;
    asm("tanh.approx.f32 %0, %1;" : "=f"(y) : "f"(x));
    return y;
}

struct UC {
    float uf00, uf01, uf10, uf11;
    float ui0, ui1, uo0, uo1, uc0, uc1;
};

__device__ __forceinline__ void cell_w(const uint32_t qw[3], const UC& u,
                                       float hup, float hl,
                                       float sup, float sl,
                                       float& s, float& h)
{
    float2 qa = up2(qw[0]);   // (f0, f1)
    float2 qb = up2(qw[1]);   // (i, o)
    float2 qcv = up2(qw[2]);  // (c, pad)
    float pf0 = fmaf(u.uf01, hl, fmaf(u.uf00, hup, qa.x));
    float pf1 = fmaf(u.uf11, hl, fmaf(u.uf10, hup, qa.y));
    float pi  = fmaf(u.ui1,  hl, fmaf(u.ui0,  hup, qb.x));
    float po  = fmaf(u.uo1,  hl, fmaf(u.uo0,  hup, qb.y));
    float pc  = fmaf(u.uc1,  hl, fmaf(u.uc0,  hup, qcv.x));
    float f0 = sigf(pf0);
    float f1 = sigf(pf1);
    float ig = sigf(pi);
    float og = sigf(po);
    float cg = sigf(pc);
    s = fmaf(f0, sup, fmaf(f1, sl, ig * cg));
    h = og * tanhapx(s);
}

// block = (b, o-group of 32). 16 warps; warp w owns rows 4w..4w+3; lane = o.
__global__ void __launch_bounds__(512, 1) mdlstm_rec_kernel(
    const float* __restrict__ uf, const float* __restrict__ ui,
    const float* __restrict__ uo, const float* __restrict__ uc,
    float* __restrict__ out)
{
    __shared__ float sh_s[4][16][32];
    __shared__ float sh_h[4][16][32];
    __shared__ int   ready[16];

    const int lane = threadIdx.x & 31;
    const int w    = threadIdx.x >> 5;     // 0..15
    const int b    = blockIdx.x >> 2;
    const int og   = blockIdx.x & 3;
    const int o    = og * 32 + lane;

    if (threadIdx.x < 16) ready[threadIdx.x] = -1;
    __syncthreads();
    const uint32_t raddr  = smem_u32(ready);
    const uint32_t r_prev = raddr + 4u * (uint32_t)(w - 1);
    const uint32_t r_next = raddr + 4u * (uint32_t)(w + 1);
    const uint32_t r_self = raddr + 4u * (uint32_t)w;

    UC u;
    u.uf00 = uf[o];        u.uf01 = uf[128 + o];
    u.uf10 = uf[256 + o];  u.uf11 = uf[384 + o];
    u.ui0  = ui[o];        u.ui1  = ui[128 + o];
    u.uo0  = uo[o];        u.uo1  = uo[128 + o];
    u.uc0  = uc[o];        u.uc1  = uc[128 + o];

    const uint32_t* preb = g_pk + (size_t)b * NPW + o;
    float* outb = out + b * 128 + o;

    const uint32_t* pbase[4];
    float* obase[4];
#pragma unroll
    for (int j = 0; j < 4; j++) {
        int r = 4 * w + j;
        pbase[j] = preb + (size_t)(r * 64) * CSTRIDE;
        obase[j] = outb + (size_t)(r * 64) * 4096;
    }

    uint32_t buf[4][4][3];
#pragma unroll
    for (int p = 0; p < 4; p++) {
#pragma unroll
        for (int j = 0; j < 4; j++) {
            int col = p - j; col = col < 0 ? 0 : col;
            const uint32_t* q = pbase[j] + (size_t)col * CSTRIDE;
            buf[p][j][0] = __ldg(q);
            buf[p][j][1] = __ldg(q + 128);
            buf[p][j][2] = __ldg(q + 256);
        }
    }

    float sj[4] = {0.f, 0.f, 0.f, 0.f};
    float hj[4] = {0.f, 0.f, 0.f, 0.f};

#define REC_BODY(S, SLOT)                                                     \
    {                                                                         \
        const int s = (S);                                                    \
        float os0 = sj[0], oh0 = hj[0];                                       \
        float os1 = sj[1], oh1 = hj[1];                                       \
        float os2 = sj[2], oh2 = hj[2];                                       \
        /* row 0 */                                                           \
        if (s <= 63) {                                                        \
            float sup, hup;                                                   \
            if (w == 0) { sup = 0.f; hup = 0.f; }                             \
            else {                                                            \
                const int need = s + 3;                                       \
                int v;                                                        \
                do {                                                          \
                    asm volatile("ld.acquire.cta.shared.b32 %0, [%1];"        \
                                 : "=r"(v) : "r"(r_prev) : "memory");         \
                } while (v < need);                                           \
                sup = sh_s[(s + 3) & 3][w - 1][lane];                         \
                hup = sh_h[(s + 3) & 3][w - 1][lane];                         \
            }                                                                 \
            float sv, hv;                                                     \
            cell_w(buf[SLOT][0], u, hup, hj[0], sup, sj[0], sv, hv);          \
            obase[0][(size_t)s * 4096] = sv;                                  \
            sj[0] = sv; hj[0] = hv;                                           \
        }                                                                     \
        /* rows 1..3 */                                                       \
        if (s >= 1 && s <= 64) {                                              \
            float sv, hv;                                                     \
            cell_w(buf[SLOT][1], u, oh0, hj[1], os0, sj[1], sv, hv);          \
            obase[1][(size_t)(s - 1) * 4096] = sv;                            \
            sj[1] = sv; hj[1] = hv;                                           \
        }                                                                     \
        if (s >= 2 && s <= 65) {                                              \
            float sv, hv;                                                     \
            cell_w(buf[SLOT][2], u, oh1, hj[2], os1, sj[2], sv, hv);          \
            obase[2][(size_t)(s - 2) * 4096] = sv;                            \
            sj[2] = sv; hj[2] = hv;                                           \
        }                                                                     \
        if (s >= 3 && s <= 66) {                                              \
            float sv, hv;                                                     \
            cell_w(buf[SLOT][3], u, oh2, hj[3], os2, sj[3], sv, hv);          \
            obase[3][(size_t)(s - 3) * 4096] = sv;                            \
            sj[3] = sv; hj[3] = hv;                                           \
            if (w < 15) {                                                     \
                const int needc = s - 7;                                      \
                if (needc >= 0) {                                             \
                    int v;                                                    \
                    do {                                                      \
                        asm volatile("ld.acquire.cta.shared.b32 %0, [%1];"    \
                                     : "=r"(v) : "r"(r_next) : "memory");     \
                    } while (v < needc);                                      \
                }                                                             \
                sh_s[SLOT][w][lane] = sv;                                     \
                sh_h[SLOT][w][lane] = hv;                                     \
            }                                                                 \
        }                                                                     \
        if (lane == 0) {                                                      \
            asm volatile("st.release.cta.shared.b32 [%0], %1;"                \
                         :: "r"(r_self), "r"(s) : "memory");                  \
        }                                                                     \
        _Pragma("unroll")                                                     \
        for (int j = 0; j < 4; j++) {                                         \
            int col = s + 4 - j;                                              \
            col = col < 0 ? 0 : (col > 63 ? 63 : col);                        \
            const uint32_t* q = pbase[j] + (size_t)col * CSTRIDE;             \
            buf[SLOT][j][0] = __ldg(q);                                       \
            buf[SLOT][j][1] = __ldg(q + 128);                                 \
            buf[SLOT][j][2] = __ldg(q + 256);                                 \
        }                                                                     \
    }

#pragma unroll 1
    for (int sb = 0; sb < 68; sb += 4) {
        REC_BODY(sb + 0, 0)
        REC_BODY(sb + 1, 1)
        REC_BODY(sb + 2, 2)
        REC_BODY(sb + 3, 3)
    }
#undef REC_BODY
}

// ================= launcher =================
extern "C" void kernel_launch(void* const* d_in, const int* in_sizes, int n_in,
                              void* d_out, int out_size) {
    (void)in_sizes; (void)n_in; (void)out_size;
    const float* x     = (const float*)d_in[0];
    const float* wf    = (const float*)d_in[1];
    const float* uf    = (const float*)d_in[2];
    const float* biasf = (const float*)d_in[3];
    const float* wi    = (const float*)d_in[4];
    const float* ui    = (const float*)d_in[5];
    const float* biasi = (const float*)d_in[6];
    const float* wo    = (const float*)d_in[7];
    const float* uo    = (const float*)d_in[8];
    const float* biaso = (const float*)d_in[9];
    const float* wc    = (const float*)d_in[10];
    const float* uc    = (const float*)d_in[11];
    const float* biasc = (const float*)d_in[12];
    float* out = (float*)d_out;

    cudaFuncSetAttribute(gemm_pre_hmma,
                         cudaFuncAttributeMaxDynamicSharedMemorySize, SM_TOTAL);
    gemm_pre_hmma<<<512, 512, SM_TOTAL>>>(
        x, wf, wi, wo, wc, biasf, biasi, biaso, biasc);
    mdlstm_rec_kernel<<<128, 512>>>(uf, ui, uo, uc, out);
}

// round 17
// speedup vs baseline: 2.4432x; 1.0002x over previous
#include <cuda_runtime.h>
#include <cuda_fp16.h>
#include <cstdint>
#include <cstddef>

// Problem dims
#define D1 64
#define D2 64
#define BB 32
#define II 64
#define OO 128
#define M_TOT (D1 * D2 * BB)   // 131072

// Packed pre-activations (R7 layout): [cell m][word p=0..2][o=0..127] uint32.
// word0 = (f0,f1), word1 = (i,o), word2 = (c,pad). Bias folded in.
#define NPW 384
#define CSTRIDE (32 * NPW)     // advance one grid position (fixed b) = 12288
__device__ uint32_t g_pk[(size_t)M_TOT * NPW];

// ========================= helpers =========================
__device__ __forceinline__ uint32_t smem_u32(const void* p) {
    uint32_t a;
    asm("{ .reg .u64 t; cvta.to.shared.u64 t, %1; cvt.u32.u64 %0, t; }"
        : "=r"(a) : "l"(p));
    return a;
}

__device__ __forceinline__ void ldsm_x4(uint32_t& r0, uint32_t& r1,
                                        uint32_t& r2, uint32_t& r3,
                                        uint32_t addr) {
    asm volatile("ldmatrix.sync.aligned.m8n8.x4.shared.b16 {%0,%1,%2,%3}, [%4];"
                 : "=r"(r0), "=r"(r1), "=r"(r2), "=r"(r3) : "r"(addr));
}

__device__ __forceinline__ void mma_f16(float* d, const uint32_t* a,
                                        uint32_t b0, uint32_t b1) {
    asm volatile(
        "mma.sync.aligned.m16n8k16.row.col.f32.f16.f16.f32 "
        "{%0,%1,%2,%3}, {%4,%5,%6,%7}, {%8,%9}, {%0,%1,%2,%3};"
        : "+f"(d[0]), "+f"(d[1]), "+f"(d[2]), "+f"(d[3])
        : "r"(a[0]), "r"(a[1]), "r"(a[2]), "r"(a[3]), "r"(b0), "r"(b1));
}

__device__ __forceinline__ uint32_t h1(float v) {
    __half h = __float2half_rn(v);
    return (uint32_t)(*reinterpret_cast<unsigned short*>(&h));
}
__device__ __forceinline__ uint32_t packh2(float a, float b) {
    __half2 h = __floats2half2_rn(a, b);
    return *reinterpret_cast<uint32_t*>(&h);
}
__device__ __forceinline__ float2 up2(uint32_t w) {
    __half2 h = *reinterpret_cast<__half2*>(&w);
    return __half22float2(h);
}

// ================= Kernel 1: HMMA fp16 GEMM, 2 m-tiles per block ===========
// Block loads W once + BOTH X tiles (double-buffered A), one barrier, then
// computes two 128-row tiles back-to-back with no further syncs.
#define A_STR 72
#define B_STR 72

#define SM_A0 0
#define SM_A1 18432
#define SM_B  36864                       // + g*18432
#define SM_TOTAL (36864 + 5 * 18432)      // 129024

__global__ void __launch_bounds__(512, 1) gemm_pre_hmma(
    const float* __restrict__ X,
    const float* __restrict__ wf, const float* __restrict__ wi,
    const float* __restrict__ wo, const float* __restrict__ wc,
    const float* __restrict__ biasf, const float* __restrict__ biasi,
    const float* __restrict__ biaso, const float* __restrict__ biasc)
{
    extern __shared__ __align__(1024) char sm[];
    const uint32_t sbase = smem_u32(sm);
    const int tid  = threadIdx.x;
    const int lane = tid & 31;
    const int w    = tid >> 5;
    const int wm   = w >> 2;
    const int wn   = w & 3;
    const int mb0  = blockIdx.x * 256;

    // ---- load + convert BOTH X tiles: 256 rows x 64 fp32 -> fp16 ----
    {
        const float4* X4 = (const float4*)(X + (size_t)mb0 * II);
#pragma unroll
        for (int it = 0; it < 8; it++) {
            int j = tid + it * 512;          // 4096 float4 total
            float4 v = X4[j];
            int row = j >> 4;                // 0..255
            int kq  = (j & 15) * 4;
            int buf = (row >= 128);
            int r   = row & 127;
            uint32_t off = (uint32_t)(buf ? SM_A1 : SM_A0)
                         + (uint32_t)(r * (A_STR * 2) + kq * 2);
            *(uint2*)(sm + off) =
                make_uint2(h1(v.x) | (h1(v.y) << 16), h1(v.z) | (h1(v.w) << 16));
        }
    }

    // ---- load + convert + transpose ALL gate weights -> Bsm[g][n][k] ----
    {
        const int n  = tid & 127;
        const int qu = tid >> 7;
#pragma unroll 1
        for (int g = 0; g < 5; g++) {
            const float* W;
            if (g == 0)      W = wf;
            else if (g == 1) W = wf + II * OO;
            else if (g == 2) W = wi;
            else if (g == 3) W = wo;
            else             W = wc;
            char* bh = sm + SM_B + g * 18432;
#pragma unroll
            for (int i = 0; i < 8; i++) {
                int k0 = qu * 16 + 2 * i;
                float w0 = __ldg(W + (size_t)k0 * OO + n);
                float w1 = __ldg(W + (size_t)(k0 + 1) * OO + n);
                uint32_t off = (uint32_t)(n * (B_STR * 2) + k0 * 2);
                *(uint32_t*)(bh + off) = h1(w0) | (h1(w1) << 16);
            }
        }
    }
    __syncthreads();   // the ONLY block barrier

    const int lrow  = lane & 15;
    const int lcolb = (lane >> 4) * 16;
    const uint32_t aRowOff =
        (uint32_t)((wm * 32 + lrow) * (A_STR * 2) + lcolb);
    uint32_t bAddr[2];
#pragma unroll
    for (int p = 0; p < 2; p++) {
        uint32_t ro = (uint32_t)((wn * 32 + p * 16 + lrow) * (B_STR * 2) + lcolb);
        bAddr[p] = sbase + SM_B + ro;
    }

    const int qr = lane >> 2;
    const int qc = (lane & 3) * 2;

#pragma unroll 1
    for (int t2 = 0; t2 < 2; t2++) {
        const int mb = mb0 + t2 * 128;
        const uint32_t aBase = sbase + (t2 ? SM_A1 : SM_A0) + aRowOff;

        // A fragments hoisted (reused across all 5 gates)
        uint32_t aF[4][2][4];
#pragma unroll
        for (int ks = 0; ks < 4; ks++) {
            const uint32_t kb = (uint32_t)(ks * 32);
#pragma unroll
            for (int mi = 0; mi < 2; mi++)
                ldsm_x4(aF[ks][mi][0], aF[ks][mi][1], aF[ks][mi][2], aF[ks][mi][3],
                        aBase + (uint32_t)(mi * 16 * (A_STR * 2)) + kb);
        }

        // ---- gate pairs: (0,1), (2,3), (4,-) ----
#pragma unroll 1
        for (int pr = 0; pr < 3; pr++) {
            const int gA = 2 * pr;
            const bool hasB = (pr < 2);
            const float* biasA;
            const float* biasB = biasc;
            if (pr == 0)      { biasA = biasf; biasB = biasf + OO; }
            else if (pr == 1) { biasA = biasi; biasB = biaso;      }
            else              { biasA = biasc;                     }
            const uint32_t gAoff = (uint32_t)(gA * 18432);
            const uint32_t gBoff = gAoff + 18432;

            float accA[2][4][4], accB[2][4][4];
#pragma unroll
            for (int mi = 0; mi < 2; mi++)
#pragma unroll
                for (int ni = 0; ni < 4; ni++)
#pragma unroll
                    for (int e = 0; e < 4; e++) { accA[mi][ni][e] = 0.f; accB[mi][ni][e] = 0.f; }

#pragma unroll
            for (int ks = 0; ks < 4; ks++) {
                const uint32_t kb = (uint32_t)(ks * 32);
#pragma unroll
                for (int pq = 0; pq < 2; pq++) {
                    uint32_t b0, b1, b2, b3;
                    ldsm_x4(b0, b1, b2, b3, bAddr[pq] + gAoff + kb);
#pragma unroll
                    for (int mi = 0; mi < 2; mi++) {
                        mma_f16(accA[mi][2 * pq],     aF[ks][mi], b0, b2);
                        mma_f16(accA[mi][2 * pq + 1], aF[ks][mi], b1, b3);
                    }
                    if (hasB) {
                        uint32_t c0, c1, c2, c3;
                        ldsm_x4(c0, c1, c2, c3, bAddr[pq] + gBoff + kb);
#pragma unroll
                        for (int mi = 0; mi < 2; mi++) {
                            mma_f16(accB[mi][2 * pq],     aF[ks][mi], c0, c2);
                            mma_f16(accB[mi][2 * pq + 1], aF[ks][mi], c1, c3);
                        }
                    }
                }
            }

            // ---- epilogue: pack two gates into one uint32 word, uint2 stores ----
#pragma unroll
            for (int ni = 0; ni < 4; ni++) {
                int col = wn * 32 + ni * 8 + qc;
                float bA0 = __ldg(biasA + col);
                float bA1 = __ldg(biasA + col + 1);
                float bB0 = hasB ? __ldg(biasB + col)     : 0.f;
                float bB1 = hasB ? __ldg(biasB + col + 1) : 0.f;
#pragma unroll
                for (int mi = 0; mi < 2; mi++) {
                    int row = mb + wm * 32 + mi * 16 + qr;
                    size_t idx = (size_t)row * NPW + (size_t)pr * 128 + col;
                    uint32_t w0, w1, w2, w3;
                    if (hasB) {
                        w0 = packh2(accA[mi][ni][0] + bA0, accB[mi][ni][0] + bB0);
                        w1 = packh2(accA[mi][ni][1] + bA1, accB[mi][ni][1] + bB1);
                        w2 = packh2(accA[mi][ni][2] + bA0, accB[mi][ni][2] + bB0);
                        w3 = packh2(accA[mi][ni][3] + bA1, accB[mi][ni][3] + bB1);
                    } else {
                        w0 = h1(accA[mi][ni][0] + bA0);
                        w1 = h1(accA[mi][ni][1] + bA1);
                        w2 = h1(accA[mi][ni][2] + bA0);
                        w3 = h1(accA[mi][ni][3] + bA1);
                    }
                    *(uint2*)(g_pk + idx) = make_uint2(w0, w1);
                    *(uint2*)(g_pk + idx + (size_t)8 * NPW) = make_uint2(w2, w3);
                }
            }
        }
    }
}

// ================= Kernel 2: wavefront recurrence (EXACT R7) ==============
__device__ __forceinline__ float sigf(float x) {
    float t;
    asm("tanh.approx.f32 %0, %1;" : "=f"(t) : "f"(0.5f * x));
    return fmaf(0.5f, t, 0.5f);
}
__device__ __forceinline__ float tanhapx(float x) {
    float y;
    asm("tanh.approx.f32 %0, %1;" : "=f"(y) : "f"(x));
    return y;
}

struct UC {
    float uf00, uf01, uf10, uf11;
    float ui0, ui1, uo0, uo1, uc0, uc1;
};

__device__ __forceinline__ void cell_w(const uint32_t qw[3], const UC& u,
                                       float hup, float hl,
                                       float sup, float sl,
                                       float& s, float& h)
{
    float2 qa = up2(qw[0]);   // (f0, f1)
    float2 qb = up2(qw[1]);   // (i, o)
    float2 qcv = up2(qw[2]);  // (c, pad)
    float pf0 = fmaf(u.uf01, hl, fmaf(u.uf00, hup, qa.x));
    float pf1 = fmaf(u.uf11, hl, fmaf(u.uf10, hup, qa.y));
    float pi  = fmaf(u.ui1,  hl, fmaf(u.ui0,  hup, qb.x));
    float po  = fmaf(u.uo1,  hl, fmaf(u.uo0,  hup, qb.y));
    float pc  = fmaf(u.uc1,  hl, fmaf(u.uc0,  hup, qcv.x));
    float f0 = sigf(pf0);
    float f1 = sigf(pf1);
    float ig = sigf(pi);
    float og = sigf(po);
    float cg = sigf(pc);
    s = fmaf(f0, sup, fmaf(f1, sl, ig * cg));
    h = og * tanhapx(s);
}

// block = (b, o-group of 32). 16 warps; warp w owns rows 4w..4w+3; lane = o.
__global__ void __launch_bounds__(512, 1) mdlstm_rec_kernel(
    const float* __restrict__ uf, const float* __restrict__ ui,
    const float* __restrict__ uo, const float* __restrict__ uc,
    float* __restrict__ out)
{
    __shared__ float sh_s[4][16][32];
    __shared__ float sh_h[4][16][32];
    __shared__ int   ready[16];

    const int lane = threadIdx.x & 31;
    const int w    = threadIdx.x >> 5;     // 0..15
    const int b    = blockIdx.x >> 2;
    const int og   = blockIdx.x & 3;
    const int o    = og * 32 + lane;

    if (threadIdx.x < 16) ready[threadIdx.x] = -1;
    __syncthreads();
    const uint32_t raddr  = smem_u32(ready);
    const uint32_t r_prev = raddr + 4u * (uint32_t)(w - 1);
    const uint32_t r_next = raddr + 4u * (uint32_t)(w + 1);
    const uint32_t r_self = raddr + 4u * (uint32_t)w;

    UC u;
    u.uf00 = uf[o];        u.uf01 = uf[128 + o];
    u.uf10 = uf[256 + o];  u.uf11 = uf[384 + o];
    u.ui0  = ui[o];        u.ui1  = ui[128 + o];
    u.uo0  = uo[o];        u.uo1  = uo[128 + o];
    u.uc0  = uc[o];        u.uc1  = uc[128 + o];

    const uint32_t* preb = g_pk + (size_t)b * NPW + o;
    float* outb = out + b * 128 + o;

    const uint32_t* pbase[4];
    float* obase[4];
#pragma unroll
    for (int j = 0; j < 4; j++) {
        int r = 4 * w + j;
        pbase[j] = preb + (size_t)(r * 64) * CSTRIDE;
        obase[j] = outb + (size_t)(r * 64) * 4096;
    }

    uint32_t buf[4][4][3];
#pragma unroll
    for (int p = 0; p < 4; p++) {
#pragma unroll
        for (int j = 0; j < 4; j++) {
            int col = p - j; col = col < 0 ? 0 : col;
            const uint32_t* q = pbase[j] + (size_t)col * CSTRIDE;
            buf[p][j][0] = __ldg(q);
            buf[p][j][1] = __ldg(q + 128);
            buf[p][j][2] = __ldg(q + 256);
        }
    }

    float sj[4] = {0.f, 0.f, 0.f, 0.f};
    float hj[4] = {0.f, 0.f, 0.f, 0.f};

#define REC_BODY(S, SLOT)                                                     \
    {                                                                         \
        const int s = (S);                                                    \
        float os0 = sj[0], oh0 = hj[0];                                       \
        float os1 = sj[1], oh1 = hj[1];                                       \
        float os2 = sj[2], oh2 = hj[2];                                       \
        /* row 0 */                                                           \
        if (s <= 63) {                                                        \
            float sup, hup;                                                   \
            if (w == 0) { sup = 0.f; hup = 0.f; }                             \
            else {                                                            \
                const int need = s + 3;                                       \
                int v;                                                        \
                do {                                                          \
                    asm volatile("ld.acquire.cta.shared.b32 %0, [%1];"        \
                                 : "=r"(v) : "r"(r_prev) : "memory");         \
                } while (v < need);                                           \
                sup = sh_s[(s + 3) & 3][w - 1][lane];                         \
                hup = sh_h[(s + 3) & 3][w - 1][lane];                         \
            }                                                                 \
            float sv, hv;                                                     \
            cell_w(buf[SLOT][0], u, hup, hj[0], sup, sj[0], sv, hv);          \
            obase[0][(size_t)s * 4096] = sv;                                  \
            sj[0] = sv; hj[0] = hv;                                           \
        }                                                                     \
        /* rows 1..3 */                                                       \
        if (s >= 1 && s <= 64) {                                              \
            float sv, hv;                                                     \
            cell_w(buf[SLOT][1], u, oh0, hj[1], os0, sj[1], sv, hv);          \
            obase[1][(size_t)(s - 1) * 4096] = sv;                            \
            sj[1] = sv; hj[1] = hv;                                           \
        }                                                                     \
        if (s >= 2 && s <= 65) {                                              \
            float sv, hv;                                                     \
            cell_w(buf[SLOT][2], u, oh1, hj[2], os1, sj[2], sv, hv);          \
            obase[2][(size_t)(s - 2) * 4096] = sv;                            \
            sj[2] = sv; hj[2] = hv;                                           \
        }                                                                     \
        if (s >= 3 && s <= 66) {                                              \
            float sv, hv;                                                     \
            cell_w(buf[SLOT][3], u, oh2, hj[3], os2, sj[3], sv, hv);          \
            obase[3][(size_t)(s - 3) * 4096] = sv;                            \
            sj[3] = sv; hj[3] = hv;                                           \
            if (w < 15) {                                                     \
                const int needc = s - 7;                                      \
                if (needc >= 0) {                                             \
                    int v;                                                    \
                    do {                                                      \
                        asm volatile("ld.acquire.cta.shared.b32 %0, [%1];"    \
                                     : "=r"(v) : "r"(r_next) : "memory");     \
                    } while (v < needc);                                      \
                }                                                             \
                sh_s[SLOT][w][lane] = sv;                                     \
                sh_h[SLOT][w][lane] = hv;                                     \
            }                                                                 \
        }                                                                     \
        if (lane == 0) {                                                      \
            asm volatile("st.release.cta.shared.b32 [%0], %1;"                \
                         :: "r"(r_self), "r"(s) : "memory");                  \
        }                                                                     \
        _Pragma("unroll")                                                     \
        for (int j = 0; j < 4; j++) {                                         \
            int col = s + 4 - j;                                              \
            col = col < 0 ? 0 : (col > 63 ? 63 : col);                        \
            const uint32_t* q = pbase[j] + (size_t)col * CSTRIDE;             \
            buf[SLOT][j][0] = __ldg(q);                                       \
            buf[SLOT][j][1] = __ldg(q + 128);                                 \
            buf[SLOT][j][2] = __ldg(q + 256);                                 \
        }                                                                     \
    }

#pragma unroll 1
    for (int sb = 0; sb < 68; sb += 4) {
        REC_BODY(sb + 0, 0)
        REC_BODY(sb + 1, 1)
        REC_BODY(sb + 2, 2)
        REC_BODY(sb + 3, 3)
    }
#undef REC_BODY
}

// ================= launcher =================
extern "C" void kernel_launch(void* const* d_in, const int* in_sizes, int n_in,
                              void* d_out, int out_size) {
    (void)in_sizes; (void)n_in; (void)out_size;
    const float* x     = (const float*)d_in[0];
    const float* wf    = (const float*)d_in[1];
    const float* uf    = (const float*)d_in[2];
    const float* biasf = (const float*)d_in[3];
    const float* wi    = (const float*)d_in[4];
    const float* ui    = (const float*)d_in[5];
    const float* biasi = (const float*)d_in[6];
    const float* wo    = (const float*)d_in[7];
    const float* uo    = (const float*)d_in[8];
    const float* biaso = (const float*)d_in[9];
    const float* wc    = (const float*)d_in[10];
    const float* uc    = (const float*)d_in[11];
    const float* biasc = (const float*)d_in[12];
    float* out = (float*)d_out;

    cudaFuncSetAttribute(gemm_pre_hmma,
                         cudaFuncAttributeMaxDynamicSharedMemorySize, SM_TOTAL);
    gemm_pre_hmma<<<512, 512, SM_TOTAL>>>(
        x, wf, wi, wo, wc, biasf, biasi, biaso, biasc);
    mdlstm_rec_kernel<<<128, 512>>>(uf, ui, uo, uc, out);
}